// round 1
// baseline (speedup 1.0000x reference)
#include <cuda_runtime.h>
#include <math.h>

#define FS   39      // total fields
#define NF   38      // fields participating in pairwise term (0..37)
#define NP   703     // NF*(NF-1)/2 pairs
#define FEAT 100000
#define EMB  10
#define TPB  256

__global__ __launch_bounds__(TPB) void ffm_kernel(
    const int*   __restrict__ idxs,   // [B, FS]
    const float* __restrict__ vals,   // [B, FS]
    const float* __restrict__ emb,    // [FS, FEAT, EMB]
    const float* __restrict__ w1,     // [FEAT]
    float*       __restrict__ out)    // [B]
{
    __shared__ int   s_idx[FS];
    __shared__ float s_val[FS];
    __shared__ unsigned char s_i[NP];
    __shared__ unsigned char s_j[NP];
    __shared__ float s_red[TPB / 32];

    const int b = blockIdx.x;
    const int t = threadIdx.x;

    if (t < FS) {
        s_idx[t] = idxs[b * FS + t];
        s_val[t] = vals[b * FS + t];
    }
    // Cooperative pair-table fill: thread i owns row i of the upper triangle.
    if (t < NF - 1) {
        const int i = t;
        const int base = i * (2 * NF - i - 1) / 2;
        #pragma unroll 1
        for (int j = i + 1; j < NF; j++) {
            s_i[base + j - i - 1] = (unsigned char)i;
            s_j[base + j - i - 1] = (unsigned char)j;
        }
    }
    __syncthreads();

    float acc = 0.f;

    // First-order term: one gather per field, folded into the reduction.
    if (t < FS) {
        acc = w1[s_idx[t]] * s_val[t];
    }

    // Second-order term: strided over pairs. Each pair: two 40B random-gather
    // rows (5x float2 each -> 10 LDG.64 in flight), dot, scale, accumulate.
    for (int p = t; p < NP; p += TPB) {
        const int i = s_i[p];
        const int j = s_j[p];
        const float2* __restrict__ A =
            (const float2*)(emb + ((size_t)i * FEAT + s_idx[j]) * EMB);
        const float2* __restrict__ B =
            (const float2*)(emb + ((size_t)j * FEAT + s_idx[i]) * EMB);
        float2 a0 = A[0], a1 = A[1], a2 = A[2], a3 = A[3], a4 = A[4];
        float2 b0 = B[0], b1 = B[1], b2 = B[2], b3 = B[3], b4 = B[4];
        float dot = a0.x * b0.x + a0.y * b0.y
                  + a1.x * b1.x + a1.y * b1.y
                  + a2.x * b2.x + a2.y * b2.y
                  + a3.x * b3.x + a3.y * b3.y
                  + a4.x * b4.x + a4.y * b4.y;
        acc += dot * s_val[i] * s_val[j];
    }

    // Block reduction.
    #pragma unroll
    for (int o = 16; o > 0; o >>= 1)
        acc += __shfl_down_sync(0xffffffffu, acc, o);
    if ((t & 31) == 0) s_red[t >> 5] = acc;
    __syncthreads();
    if (t == 0) {
        float tot = 0.f;
        #pragma unroll
        for (int w = 0; w < TPB / 32; w++) tot += s_red[w];
        out[b] = 1.f / (1.f + expf(-tot));
    }
}

extern "C" void kernel_launch(void* const* d_in, const int* in_sizes, int n_in,
                              void* d_out, int out_size) {
    const int*   idxs = (const int*)d_in[0];
    const float* vals = (const float*)d_in[1];
    const float* emb  = (const float*)d_in[2];
    const float* w1   = (const float*)d_in[3];
    float* out = (float*)d_out;

    const int batch = out_size;  // 2048
    ffm_kernel<<<batch, TPB>>>(idxs, vals, emb, w1, out);
}